// round 11
// baseline (speedup 1.0000x reference)
#include <cuda_runtime.h>

#define BATCH 4096
#define SEQT  256
#define DIN   32
#define HID   64
#define GATES 256
#define BT    32
#define NTHR  512
#define NCTA  128
#define ST    36

typedef unsigned long long u64;

// ---- gate-quad weight layout W[k][u2][g][upar]: n = g*64 + u2*2 + up (R9-proven) ----
__device__ __align__(16) float g_W0q[HID * GATES];     // Whh0 quad
__device__ __align__(16) float g_Wx0q[DIN * GATES];    // Wih0 quad (per-step LDG)
__device__ __align__(16) float g_W1q[2 * HID * GATES]; // [Wih1; Whh1] quad
__device__ __align__(16) float g_b0q[GATES];
__device__ __align__(16) float g_b1q[GATES];

__global__ void prep_kernel(const float* __restrict__ Wih0, const float* __restrict__ Whh0,
                            const float* __restrict__ bih0, const float* __restrict__ bhh0,
                            const float* __restrict__ Wih1, const float* __restrict__ Whh1,
                            const float* __restrict__ bih1, const float* __restrict__ bhh1)
{
    int idx = blockIdx.x * blockDim.x + threadIdx.x;
    int stride = gridDim.x * blockDim.x;
    for (int j = idx; j < HID * GATES; j += stride) {
        int k = j / GATES, r = j % GATES;
        int n = ((r >> 1) & 3) * HID + (r >> 3) * 2 + (r & 1);
        g_W0q[j] = Whh0[n * HID + k];
    }
    for (int j = idx; j < DIN * GATES; j += stride) {
        int k = j / GATES, r = j % GATES;
        int n = ((r >> 1) & 3) * HID + (r >> 3) * 2 + (r & 1);
        g_Wx0q[j] = Wih0[n * DIN + k];
    }
    for (int j = idx; j < 2 * HID * GATES; j += stride) {
        int k = j / GATES, r = j % GATES;
        int n = ((r >> 1) & 3) * HID + (r >> 3) * 2 + (r & 1);
        g_W1q[j] = (k < HID) ? Wih1[n * HID + k] : Whh1[n * HID + (k - HID)];
    }
    for (int r = idx; r < GATES; r += stride) {
        int n = ((r >> 1) & 3) * HID + (r >> 3) * 2 + (r & 1);
        g_b0q[r] = bih0[n] + bhh0[n];
        g_b1q[r] = bih1[n] + bhh1[n];
    }
}

// ---- packed f32x2 helpers ----
__device__ __forceinline__ u64 fma2(u64 a, u64 b, u64 c) {
    u64 d;
    asm("fma.rn.f32x2 %0, %1, %2, %3;" : "=l"(d) : "l"(a), "l"(b), "l"(c));
    return d;
}
__device__ __forceinline__ u64 dup2(float x) {
    u64 d;
    asm("mov.b64 %0, {%1, %1};" : "=l"(d) : "f"(x));
    return d;
}
__device__ __forceinline__ float2 unpack2(u64 v) {
    float2 f;
    asm("mov.b64 {%0, %1}, %2;" : "=f"(f.x), "=f"(f.y) : "l"(v));
    return f;
}

// ---- fast activations (MUFU EX2/RCP, proven ~2.5e-7 end-to-end) ----
__device__ __forceinline__ float fast_ex2(float x) {
    float y; asm("ex2.approx.f32 %0, %1;" : "=f"(y) : "f"(x)); return y;
}
__device__ __forceinline__ float fast_rcp(float x) {
    float y; asm("rcp.approx.f32 %0, %1;" : "=f"(y) : "f"(x)); return y;
}
__device__ __forceinline__ float sigf(float x) {
    return fast_rcp(1.0f + fast_ex2(-1.4426950408889634f * x));
}
__device__ __forceinline__ float tanhf_fast(float x) {
    x = fminf(fmaxf(x, -15.0f), 15.0f);
    float e = fast_ex2(-2.8853900817779268f * x);
    return (1.0f - e) * fast_rcp(1.0f + e);
}

// GEMM fragment (quad layout): 2 rows x 8 gate-cols; per k: 1 LDS.64 act + 2 LDS.128 w
template <bool GW, int K>
__device__ __forceinline__ void gemm_q2(const float* __restrict__ aT,
                                        const float* __restrict__ Wq,
                                        int m0, int w8, u64 acc[2][4])
{
#pragma unroll 4
    for (int k = 0; k < K; k++) {
        float2 hv = *(const float2*)(aT + k * ST + m0);
        const float* wp = Wq + k * GATES + w8;
        ulonglong2 wv0, wv1;
        if (GW) {
            wv0 = __ldg((const ulonglong2*)wp);
            wv1 = __ldg((const ulonglong2*)(wp + 4));
        } else {
            wv0 = *(const ulonglong2*)wp;
            wv1 = *(const ulonglong2*)(wp + 4);
        }
        u64 a0 = dup2(hv.x);
        acc[0][0] = fma2(a0, wv0.x, acc[0][0]);
        acc[0][1] = fma2(a0, wv0.y, acc[0][1]);
        acc[0][2] = fma2(a0, wv1.x, acc[0][2]);
        acc[0][3] = fma2(a0, wv1.y, acc[0][3]);
        u64 a1 = dup2(hv.y);
        acc[1][0] = fma2(a1, wv0.x, acc[1][0]);
        acc[1][1] = fma2(a1, wv0.y, acc[1][1]);
        acc[1][2] = fma2(a1, wv1.x, acc[1][2]);
        acc[1][3] = fma2(a1, wv1.y, acc[1][3]);
    }
}

__device__ __forceinline__ void acc_init2(const float* __restrict__ sB, int w8, u64 acc[2][4])
{
    ulonglong2 b0 = *(const ulonglong2*)(sB + w8);
    ulonglong2 b1 = *(const ulonglong2*)(sB + w8 + 4);
    acc[0][0] = b0.x; acc[0][1] = b0.y; acc[0][2] = b1.x; acc[0][3] = b1.y;
    acc[1][0] = b0.x; acc[1][1] = b0.y; acc[1][2] = b1.x; acc[1][3] = b1.y;
}

// update 2 rows x 2 cells; rows m0, m0+1; cells u0, u0+1
__device__ __forceinline__ void lstm_update2(const u64 acc[2][4], float c[2][2],
                                             float* __restrict__ hT, int m0, int u0)
{
    float h[2][2];
#pragma unroll
    for (int r = 0; r < 2; r++) {
        float2 pi = unpack2(acc[r][0]);
        float2 pf = unpack2(acc[r][1]);
        float2 pg = unpack2(acc[r][2]);
        float2 po = unpack2(acc[r][3]);
        {
            float iv = sigf(pi.x), fv = sigf(pf.x), gv = tanhf_fast(pg.x), ov = sigf(po.x);
            float cc = fv * c[r][0] + iv * gv;
            c[r][0] = cc;
            h[r][0] = ov * tanhf_fast(cc);
        }
        {
            float iv = sigf(pi.y), fv = sigf(pf.y), gv = tanhf_fast(pg.y), ov = sigf(po.y);
            float cc = fv * c[r][1] + iv * gv;
            c[r][1] = cc;
            h[r][1] = ov * tanhf_fast(cc);
        }
    }
    *(float2*)(hT + (u0 + 0) * ST + m0) = make_float2(h[0][0], h[1][0]);
    *(float2*)(hT + (u0 + 1) * ST + m0) = make_float2(h[0][1], h[1][1]);
}

// Shared layout (floats)
#define OFF_W0   0
#define OFF_W1   (OFF_W0 + HID * GATES)
#define OFF_B0   (OFF_W1 + 2 * HID * GATES)
#define OFF_B1   (OFF_B0 + GATES)
#define OFF_H0T  (OFF_B1 + GATES)
#define OFF_H1T  (OFF_H0T + HID * ST)
#define OFF_XT   (OFF_H1T + HID * ST)
#define SMEM_FLOATS (OFF_XT + DIN * ST)   // 221696 B

__global__ void __launch_bounds__(NTHR, 1)
lstm_fused(const float* __restrict__ x,
           const float* __restrict__ W1h, const float* __restrict__ b1h,
           const float* __restrict__ W2h, const float* __restrict__ b2h,
           float* __restrict__ out)
{
    extern __shared__ float sm[];
    float* sW0 = sm + OFF_W0;
    float* sW1 = sm + OFF_W1;
    float* sB0 = sm + OFF_B0;
    float* sB1 = sm + OFF_B1;
    float* h0T = sm + OFF_H0T;
    float* h1T = sm + OFF_H1T;
    float* xT  = sm + OFF_XT;

    const int tid = threadIdx.x;
    const int b0  = blockIdx.x * BT;

    // stage weights + zero states (whole CTA)
    for (int i = tid; i < HID * GATES / 4; i += NTHR)
        ((float4*)sW0)[i] = ((const float4*)g_W0q)[i];
    for (int i = tid; i < 2 * HID * GATES / 4; i += NTHR)
        ((float4*)sW1)[i] = ((const float4*)g_W1q)[i];
    if (tid < GATES) { sB0[tid] = g_b0q[tid]; sB1[tid] = g_b1q[tid]; }
    for (int i = tid; i < 2 * HID * ST; i += NTHR) h0T[i] = 0.0f;  // h0T+h1T contiguous

    // ---- two independent groups of 256 threads; group g owns rows [16g, 16g+16) ----
    const int grp  = tid >> 8;          // 0 or 1
    const int tg   = tid & 255;
    const int barid = grp + 1;          // named barriers 1 and 2 (0 = syncthreads)
    const int gm = tg & 7;
    const int gn = tg >> 3;             // 0..31
    const int m0 = grp * 16 + gm * 2;   // 2 rows per thread
    const int u0 = gn * 2;              // 2 cells
    const int w8 = gn * 8;              // quad block offset

    float c0[2][2] = {{0.f, 0.f}, {0.f, 0.f}};
    float c1[2][2] = {{0.f, 0.f}, {0.f, 0.f}};
    u64 acc0[2][4], acc1[2][4];

    // x staging within group: 16 rows x 16 float2-chunks
    const int xm = grp * 16 + (tg >> 4);
    const int xd = tg & 15;
    const float* xrow = x + (size_t)(b0 + xm) * SEQT * DIN + xd * 2;

    // prologue: stage x(0)
    float2 xv = *(const float2*)(xrow);
    xT[(2 * xd + 0) * ST + xm] = xv.x;
    xT[(2 * xd + 1) * ST + xm] = xv.y;
    __syncthreads();

    // gemm0(0): acc0 = b0 + Wih0*x(0) + Whh0*0
    acc_init2(sB0, w8, acc0);
    gemm_q2<true, DIN>(xT, g_Wx0q, m0, w8, acc0);
    gemm_q2<false, HID>(h0T, sW0, m0, w8, acc0);
    xv = *(const float2*)(xrow + DIN);   // x(1)

    for (int t = 0; t < SEQT; t++) {
        asm volatile("bar.sync %0, 256;" :: "r"(barid) : "memory");  // B1: gemm0(t) reads done

        // update0 -> h0(t); stage x(t+1)
        lstm_update2(acc0, c0, h0T, m0, u0);
        xT[(2 * xd + 0) * ST + xm] = xv.x;
        xT[(2 * xd + 1) * ST + xm] = xv.y;
        {
            int tn = (t + 2 < SEQT) ? t + 2 : SEQT - 1;
            xv = *(const float2*)(xrow + (size_t)tn * DIN);
        }
        asm volatile("bar.sync %0, 256;" :: "r"(barid) : "memory");  // B2: h0(t), x(t+1) visible

        // gemm1: b1 + Wih1*h0(t) + Whh1*h1(t-1)
        acc_init2(sB1, w8, acc1);
        gemm_q2<false, HID>(h0T, sW1, m0, w8, acc1);
        gemm_q2<false, HID>(h1T, sW1 + HID * GATES, m0, w8, acc1);
        asm volatile("bar.sync %0, 256;" :: "r"(barid) : "memory");  // B3: h1(t-1) reads done

        // gemm0(t+1) (FFMA) overlaps update1 (MUFU); other group covers barrier gaps
        if (t + 1 < SEQT) {
            acc_init2(sB0, w8, acc0);
            gemm_q2<true, DIN>(xT, g_Wx0q, m0, w8, acc0);
            gemm_q2<false, HID>(h0T, sW0, m0, w8, acc0);
        }
        lstm_update2(acc1, c1, h1T, m0, u0);    // writes h1(t)
    }
    __syncthreads();

    // ---- head: out[m] = b2 + sum_n W2[n]*relu(b1[n] + sum_k h1(k,m) W1[n,k]) ----
    {
        int m = tid >> 4;      // 0..31
        int q = tid & 15;      // 0..15
        float pm = 0.0f;
#pragma unroll
        for (int jj = 0; jj < 4; jj++) {
            int n = q * 4 + jj;
            float sv = b1h[n];
#pragma unroll 8
            for (int k = 0; k < HID; k++)
                sv += h1T[k * ST + m] * W1h[n * HID + k];
            pm += fmaxf(sv, 0.0f) * W2h[n];
        }
#pragma unroll
        for (int off = 8; off > 0; off >>= 1)
            pm += __shfl_down_sync(0xffffffffu, pm, off, 16);
        if (q == 0) out[b0 + m] = pm + b2h[0];
    }
}

extern "C" void kernel_launch(void* const* d_in, const int* in_sizes, int n_in,
                              void* d_out, int out_size)
{
    const float* x    = (const float*)d_in[0];
    const float* Wih0 = (const float*)d_in[1];
    const float* Whh0 = (const float*)d_in[2];
    const float* bih0 = (const float*)d_in[3];
    const float* bhh0 = (const float*)d_in[4];
    const float* Wih1 = (const float*)d_in[5];
    const float* Whh1 = (const float*)d_in[6];
    const float* bih1 = (const float*)d_in[7];
    const float* bhh1 = (const float*)d_in[8];
    const float* W1   = (const float*)d_in[9];
    const float* b1   = (const float*)d_in[10];
    const float* W2   = (const float*)d_in[11];
    const float* b2   = (const float*)d_in[12];

    prep_kernel<<<64, 256>>>(Wih0, Whh0, bih0, bhh0, Wih1, Whh1, bih1, bhh1);

    size_t smem_bytes = (size_t)SMEM_FLOATS * sizeof(float);
    cudaFuncSetAttribute(lstm_fused,
                         cudaFuncAttributeMaxDynamicSharedMemorySize, (int)smem_bytes);
    lstm_fused<<<NCTA, NTHR, smem_bytes>>>(x, W1, b1, W2, b2, (float*)d_out);
}